// round 16
// baseline (speedup 1.0000x reference)
#include <cuda_runtime.h>
#include <cuda_fp16.h>
#include <cstdint>

// ============ sm_103-safe primitives ============
__device__ __forceinline__ uint32_t smem_u32(const void* p) {
    uint32_t a;
    asm("{ .reg .u64 t; cvta.to.shared.u64 t, %1; cvt.u32.u64 %0, t; }" : "=r"(a) : "l"(p));
    return a;
}
__device__ __forceinline__ void ldsm4(uint32_t r[4], uint32_t addr) {
    asm volatile("ldmatrix.sync.aligned.m8n8.x4.shared.b16 {%0,%1,%2,%3}, [%4];"
                 : "=r"(r[0]), "=r"(r[1]), "=r"(r[2]), "=r"(r[3]) : "r"(addr));
}
__device__ __forceinline__ void ldsm4t(uint32_t r[4], uint32_t addr) {
    asm volatile("ldmatrix.sync.aligned.m8n8.x4.trans.shared.b16 {%0,%1,%2,%3}, [%4];"
                 : "=r"(r[0]), "=r"(r[1]), "=r"(r[2]), "=r"(r[3]) : "r"(addr));
}
__device__ __forceinline__ void mma16816(float c[4], const uint32_t a[4],
                                         uint32_t b0, uint32_t b1) {
    asm volatile(
        "mma.sync.aligned.m16n8k16.row.col.f32.f16.f16.f32 "
        "{%0,%1,%2,%3},{%4,%5,%6,%7},{%8,%9},{%0,%1,%2,%3};"
        : "+f"(c[0]), "+f"(c[1]), "+f"(c[2]), "+f"(c[3])
        : "r"(a[0]), "r"(a[1]), "r"(a[2]), "r"(a[3]), "r"(b0), "r"(b1));
}
__device__ __forceinline__ uint32_t pack2h(__half lo, __half hi) {
    return ((uint32_t)__half_as_ushort(hi) << 16) | (uint32_t)__half_as_ushort(lo);
}
__device__ __forceinline__ uint2 cvt4h(float4 v) {
    return make_uint2(pack2h(__float2half_rn(v.x), __float2half_rn(v.y)),
                      pack2h(__float2half_rn(v.z), __float2half_rn(v.w)));
}
__device__ __forceinline__ void cpa16(uint32_t dst, const void* src) {
    asm volatile("cp.async.cg.shared.global [%0], [%1], 16;" :: "r"(dst), "l"(src) : "memory");
}
#define CP_COMMIT() asm volatile("cp.async.commit_group;" ::: "memory")
#define CP_WAIT0()  asm volatile("cp.async.wait_group 0;" ::: "memory")
#define SWZ128(o) ((o) ^ (((o) >> 3) & 0x70))
#define SWZ256(o) ((o) ^ (((o) >> 4) & 0x70))

// ============ problem constants ============
#define FIN  1024
#define SEQ  128
#define CH   128           // K per chunk
#define NC   8             // chunks

// ============ pre-converted global staging (single fp16) ============
__device__ __align__(16) __half g_Wq[1024 * 1024];
__device__ __align__(16) __half g_Wk[1024 * 1024];
__device__ __align__(16) __half g_x[256 * 1024 * 128];

__global__ void __launch_bounds__(256) prep_w_kernel(const float* __restrict__ Wq,
                                                     const float* __restrict__ Wk) {
    int base = blockIdx.x * 1024 + threadIdx.x;
    float4 v0 = ((const float4*)Wq)[base];
    float4 v1 = ((const float4*)Wq)[base + 256];
    float4 v2 = ((const float4*)Wq)[base + 512];
    float4 v3 = ((const float4*)Wq)[base + 768];
    float4 u0 = ((const float4*)Wk)[base];
    float4 u1 = ((const float4*)Wk)[base + 256];
    float4 u2 = ((const float4*)Wk)[base + 512];
    float4 u3 = ((const float4*)Wk)[base + 768];
    ((uint2*)g_Wq)[base]       = cvt4h(v0);
    ((uint2*)g_Wq)[base + 256] = cvt4h(v1);
    ((uint2*)g_Wq)[base + 512] = cvt4h(v2);
    ((uint2*)g_Wq)[base + 768] = cvt4h(v3);
    ((uint2*)g_Wk)[base]       = cvt4h(u0);
    ((uint2*)g_Wk)[base + 256] = cvt4h(u1);
    ((uint2*)g_Wk)[base + 512] = cvt4h(u2);
    ((uint2*)g_Wk)[base + 768] = cvt4h(u3);
}
__global__ void __launch_bounds__(256) prep_x_kernel(const float* __restrict__ x) {
    size_t base = (size_t)blockIdx.x * 1024 + threadIdx.x;
    float4 v0 = ((const float4*)x)[base];
    float4 v1 = ((const float4*)x)[base + 256];
    float4 v2 = ((const float4*)x)[base + 512];
    float4 v3 = ((const float4*)x)[base + 768];
    ((uint2*)g_x)[base]       = cvt4h(v0);
    ((uint2*)g_x)[base + 256] = cvt4h(v1);
    ((uint2*)g_x)[base + 512] = cvt4h(v2);
    ((uint2*)g_x)[base + 768] = cvt4h(v3);
}

// ============ SMEM layout (bytes) ============
// 2-stage chunk buffers: [W 256x128 fp16 64K | x 128x128 fp16 32K] x 2 = 192K
#define BUF_SZ  98304
#define BW_S    0
#define BX_S    65536
#define KT_S    98304          // overlays buffer-1 region (dead after mainloop+sync)
#define QT_S    196608         // 2 heads x [128 s][64 d] fp16 (16K/head)
#define W_SM    229376
#define BQ_SM   230400
#define BK_SM   230912
#define WO_SM   231424
#define SMEM_TOTAL 231936

__global__ void __launch_bounds__(256, 1)
Attention_75402445849133_kernel(const float* __restrict__ bq, const float* __restrict__ bk,
                                const float* __restrict__ Wo, const float* __restrict__ bo,
                                float* __restrict__ out)
{
    extern __shared__ char smem[];
    const uint32_t sbase = smem_u32(smem);
    const int tid = threadIdx.x;
    const int w   = tid >> 5;
    const int lid = tid & 31;
    const int gq  = lid >> 2;
    const int tq  = lid & 3;
    const int g   = blockIdx.x;
    const int b0i = blockIdx.y;    // item 0 batch; item 1 = b0i + 128

    float* wsm = (float*)(smem + W_SM);
    float* bqs = (float*)(smem + BQ_SM);
    float* bks = (float*)(smem + BK_SM);
    float* wos = (float*)(smem + WO_SM);
    if (tid < 128) {
        bqs[tid] = bq[g * 128 + tid];
        bks[tid] = bk[g * 128 + tid];
        wos[tid] = Wo[tid];
    }
    wsm[tid] = 0.0f;

    const __half* Wqb = g_Wq + (size_t)g * 128 * FIN;
    const __half* Wkb = g_Wk + (size_t)g * 128 * FIN;

    const int m0 = (w & 3) * 64;
    const int n0 = (w >> 2) * 64;
    const int tL = lid >> 3;

    // prologue: issue item-0 chunk 0 into buffer 0
    {
        const __half* xbh = g_x + (size_t)b0i * FIN * SEQ;
        #pragma unroll
        for (int j = 0; j < 16; j++) {
            int wi = j * 256 + tid;
            int row = wi >> 4, cg = wi & 15;
            uint32_t off = SWZ256((uint32_t)(row * 256 + cg * 16));
            const __half* src = (row < 128 ? Wqb : Wkb) + (size_t)(row & 127) * FIN + cg * 8;
            cpa16(sbase + BW_S + off, src);
        }
        #pragma unroll
        for (int j = 0; j < 8; j++) {
            int xi = j * 256 + tid;
            int xr = xi >> 4, xg = xi & 15;
            uint32_t off = SWZ256((uint32_t)(xr * 256 + xg * 16));
            cpa16(sbase + BX_S + off, xbh + (size_t)xr * SEQ + xg * 8);
        }
        CP_COMMIT();
    }

    #pragma unroll 1
    for (int it = 0; it < 2; it++) {
        const __half* xbh = g_x + (size_t)(b0i + it * 128) * FIN * SEQ;

        float creg[4][8][4];
        #pragma unroll
        for (int a = 0; a < 4; a++)
            #pragma unroll
            for (int n = 0; n < 8; n++)
                #pragma unroll
                for (int j = 0; j < 4; j++) creg[a][n][j] = 0.f;

        // ================= fused Q+K projection mainloop =================
        #pragma unroll 1
        for (int kc = 0; kc < NC; kc++) {
            CP_WAIT0();
            __syncthreads();

            if (kc + 1 < NC) {
                const uint32_t nb = sbase + ((kc + 1) & 1) * BUF_SZ;
                const int kn = (kc + 1) * CH;
                #pragma unroll
                for (int j = 0; j < 16; j++) {
                    int wi = j * 256 + tid;
                    int row = wi >> 4, cg = wi & 15;
                    uint32_t off = SWZ256((uint32_t)(row * 256 + cg * 16));
                    const __half* src = (row < 128 ? Wqb : Wkb) + (size_t)(row & 127) * FIN + kn + cg * 8;
                    cpa16(nb + BW_S + off, src);
                }
                #pragma unroll
                for (int j = 0; j < 8; j++) {
                    int xi = j * 256 + tid;
                    int xr = xi >> 4, xg = xi & 15;
                    uint32_t off = SWZ256((uint32_t)(xr * 256 + xg * 16));
                    cpa16(nb + BX_S + off, xbh + (size_t)(kn + xr) * SEQ + xg * 8);
                }
                CP_COMMIT();
            }

            const uint32_t bufb = sbase + (kc & 1) * BUF_SZ;
            uint32_t aA[2][4][4];
            #pragma unroll
            for (int mt = 0; mt < 4; mt++) {
                int row = m0 + mt * 16 + (lid & 15);
                int col = ((lid >> 4) << 3);
                ldsm4(aA[0][mt], bufb + BW_S + SWZ256((uint32_t)(row * 256 + col * 2)));
            }
            uint32_t bCur[4], bNxt[4];
            {
                int krw = ((tL & 1) << 3) + (lid & 7);
                int nc  = n0 + ((tL >> 1) << 3);
                ldsm4t(bCur, bufb + BX_S + SWZ256((uint32_t)(krw * 256 + nc * 2)));
            }
            #pragma unroll
            for (int step = 0; step < 32; step++) {
                const int ks = step >> 2, np = step & 3;
                const int cur = ks & 1;
                if (step < 31) {
                    int ks2 = (step + 1) >> 2, np2 = (step + 1) & 3;
                    int krw2 = ks2 * 16 + ((tL & 1) << 3) + (lid & 7);
                    int nc2  = n0 + np2 * 16 + ((tL >> 1) << 3);
                    ldsm4t(bNxt, bufb + BX_S + SWZ256((uint32_t)(krw2 * 256 + nc2 * 2)));
                }
                if (np == 0 && ks < 7) {
                    #pragma unroll
                    for (int mt = 0; mt < 4; mt++) {
                        int row = m0 + mt * 16 + (lid & 15);
                        int col = (ks + 1) * 16 + ((lid >> 4) << 3);
                        ldsm4(aA[cur ^ 1][mt], bufb + BW_S + SWZ256((uint32_t)(row * 256 + col * 2)));
                    }
                }
                #pragma unroll
                for (int mt = 0; mt < 4; mt++) mma16816(creg[mt][np * 2],     aA[cur][mt], bCur[0], bCur[1]);
                #pragma unroll
                for (int mt = 0; mt < 4; mt++) mma16816(creg[mt][np * 2 + 1], aA[cur][mt], bCur[2], bCur[3]);
                #pragma unroll
                for (int j = 0; j < 4; j++) bCur[j] = bNxt[j];
            }
        }
        __syncthreads();   // all reads of buffer 1 (chunk 7) done -> KT overlay OK

        // cross-item prefetch: issue item-1 chunk 0 into buffer 0 (free: last
        // reads were chunk 6, guarded by the kc=7 barrier). Hides the item-1
        // prologue stall under writeback + phase 2/3.
        if (it == 0) {
            const __half* xb2 = g_x + (size_t)(b0i + 128) * FIN * SEQ;
            #pragma unroll
            for (int j = 0; j < 16; j++) {
                int wi = j * 256 + tid;
                int row = wi >> 4, cg = wi & 15;
                uint32_t off = SWZ256((uint32_t)(row * 256 + cg * 16));
                const __half* src = (row < 128 ? Wqb : Wkb) + (size_t)(row & 127) * FIN + cg * 8;
                cpa16(sbase + BW_S + off, src);
            }
            #pragma unroll
            for (int j = 0; j < 8; j++) {
                int xi = j * 256 + tid;
                int xr = xi >> 4, xg = xi & 15;
                uint32_t off = SWZ256((uint32_t)(xr * 256 + xg * 16));
                cpa16(sbase + BX_S + off, xb2 + (size_t)xr * SEQ + xg * 8);
            }
            CP_COMMIT();
        }

        // ---- writeback: stacked C -> qT / kT single fp16 (+bias; q scaled 1/8)
        {
            #pragma unroll
            for (int mt = 0; mt < 4; mt++)
                #pragma unroll
                for (int rj = 0; rj < 2; rj++) {
                    int m = m0 + mt * 16 + rj * 8 + gq;
                    int isq = (m < 128);
                    int mloc = m & 127;
                    float bias = isq ? bqs[mloc] : bks[mloc];
                    int head = mloc >> 6, d = mloc & 63;
                    char* dh = smem + (isq ? QT_S : KT_S) + head * 16384;
                    #pragma unroll
                    for (int nt = 0; nt < 8; nt++)
                        #pragma unroll
                        for (int jj = 0; jj < 2; jj++) {
                            int n = n0 + nt * 8 + tq * 2 + jj;
                            float v = creg[mt][nt][rj * 2 + jj] + bias;
                            if (isq) v *= 0.125f;
                            uint32_t off = SWZ128((uint32_t)(n * 128 + d * 2));
                            *(__half*)(dh + off) = __float2half_rn(v);
                        }
                }
        }
        __syncthreads();

        // ================= Phase 2: scores + softmax + w reduction ==============
        {
            const int head = w >> 2;
            const int sb0  = (w & 3) * 32;
            const uint32_t qh = sbase + QT_S + head * 16384;
            const uint32_t kh = sbase + KT_S + head * 16384;

            float wacc[16][2];
            #pragma unroll
            for (int nt = 0; nt < 16; nt++) { wacc[nt][0] = 0.f; wacc[nt][1] = 0.f; }

            #pragma unroll 1
            for (int chunk = 0; chunk < 2; chunk++) {
                const int s0 = sb0 + chunk * 16;
                float sc[16][4];
                #pragma unroll
                for (int nt = 0; nt < 16; nt++)
                    #pragma unroll
                    for (int j = 0; j < 4; j++) sc[nt][j] = 0.f;

                #pragma unroll
                for (int ks = 0; ks < 4; ks++) {
                    const int k0 = ks * 16;
                    uint32_t aS[4];
                    {
                        int row = s0 + (lid & 15);
                        int col = k0 + ((lid >> 4) << 3);
                        uint32_t off = SWZ128((uint32_t)(row * 128 + col * 2));
                        ldsm4(aS, qh + off);
                    }
                    #pragma unroll
                    for (int npp = 0; npp < 4; npp++) {
                        int ccol = k0 + ((tL & 1) << 3);
                        int r0 = (npp * 2) * 16 + ((tL >> 1) << 3) + (lid & 7);
                        int r1 = (npp * 2 + 1) * 16 + ((tL >> 1) << 3) + (lid & 7);
                        uint32_t bH0[4], bH1[4];
                        ldsm4(bH0, kh + SWZ128((uint32_t)(r0 * 128 + ccol * 2)));
                        ldsm4(bH1, kh + SWZ128((uint32_t)(r1 * 128 + ccol * 2)));
                        mma16816(sc[npp * 4 + 0], aS, bH0[0], bH0[1]);
                        mma16816(sc[npp * 4 + 1], aS, bH0[2], bH0[3]);
                        mma16816(sc[npp * 4 + 2], aS, bH1[0], bH1[1]);
                        mma16816(sc[npp * 4 + 3], aS, bH1[2], bH1[3]);
                    }
                }
                float mx0 = -1e30f, mx1 = -1e30f;
                #pragma unroll
                for (int nt = 0; nt < 16; nt++) {
                    mx0 = fmaxf(mx0, fmaxf(sc[nt][0], sc[nt][1]));
                    mx1 = fmaxf(mx1, fmaxf(sc[nt][2], sc[nt][3]));
                }
                mx0 = fmaxf(mx0, __shfl_xor_sync(0xffffffffu, mx0, 1));
                mx0 = fmaxf(mx0, __shfl_xor_sync(0xffffffffu, mx0, 2));
                mx1 = fmaxf(mx1, __shfl_xor_sync(0xffffffffu, mx1, 1));
                mx1 = fmaxf(mx1, __shfl_xor_sync(0xffffffffu, mx1, 2));
                float Z0 = 0.f, Z1 = 0.f;
                #pragma unroll
                for (int nt = 0; nt < 16; nt++) {
                    sc[nt][0] = __expf(sc[nt][0] - mx0); Z0 += sc[nt][0];
                    sc[nt][1] = __expf(sc[nt][1] - mx0); Z0 += sc[nt][1];
                    sc[nt][2] = __expf(sc[nt][2] - mx1); Z1 += sc[nt][2];
                    sc[nt][3] = __expf(sc[nt][3] - mx1); Z1 += sc[nt][3];
                }
                Z0 += __shfl_xor_sync(0xffffffffu, Z0, 1);
                Z0 += __shfl_xor_sync(0xffffffffu, Z0, 2);
                Z1 += __shfl_xor_sync(0xffffffffu, Z1, 1);
                Z1 += __shfl_xor_sync(0xffffffffu, Z1, 2);
                const float c0 = wos[s0 + gq]     / Z0;
                const float c1 = wos[s0 + 8 + gq] / Z1;
                #pragma unroll
                for (int nt = 0; nt < 16; nt++) {
                    wacc[nt][0] += sc[nt][0] * c0 + sc[nt][2] * c1;
                    wacc[nt][1] += sc[nt][1] * c0 + sc[nt][3] * c1;
                }
            }
            #pragma unroll
            for (int d = 4; d < 32; d <<= 1)
                #pragma unroll
                for (int nt = 0; nt < 16; nt++) {
                    wacc[nt][0] += __shfl_xor_sync(0xffffffffu, wacc[nt][0], d);
                    wacc[nt][1] += __shfl_xor_sync(0xffffffffu, wacc[nt][1], d);
                }
            if (lid < 4) {
                #pragma unroll
                for (int nt = 0; nt < 16; nt++) {
                    atomicAdd(&wsm[head * 128 + nt * 8 + 2 * lid],     wacc[nt][0]);
                    atomicAdd(&wsm[head * 128 + nt * 8 + 2 * lid + 1], wacc[nt][1]);
                }
            }
        }
        __syncthreads();

        // ================= Phase 3: out = sum_t w[head][t] * x_h[b,f,t] + bo ====
        if (tid < 128) {
            const float* wv2 = wsm + (tid >> 6) * 128;
            const uint4* x8 = (const uint4*)(xbh + (size_t)(g * 128 + tid) * SEQ);
            float acc = 0.f;
            #pragma unroll 4
            for (int t8 = 0; t8 < 16; t8++) {
                uint4 v = x8[t8];
                const __half2* h = (const __half2*)&v;
                #pragma unroll
                for (int j = 0; j < 4; j++) {
                    float2 f = __half22float2(h[j]);
                    acc += f.x * wv2[t8 * 8 + j * 2] + f.y * wv2[t8 * 8 + j * 2 + 1];
                }
            }
            out[(size_t)(b0i + it * 128) * FIN + g * 128 + tid] = acc + bo[0];
        }

        if (it == 0) {
            __syncthreads();          // phase-3 reads of wsm done
            wsm[tid] = 0.0f;          // reset for item 1
        }
    }
}

extern "C" void kernel_launch(void* const* d_in, const int* in_sizes, int n_in,
                              void* d_out, int out_size)
{
    (void)in_sizes; (void)n_in; (void)out_size;
    const float* x  = (const float*)d_in[0];
    const float* Wq = (const float*)d_in[1];
    const float* bq = (const float*)d_in[2];
    const float* Wk = (const float*)d_in[3];
    const float* bk = (const float*)d_in[4];
    const float* Wo = (const float*)d_in[5];
    const float* bo = (const float*)d_in[6];
    float* out = (float*)d_out;

    prep_w_kernel<<<256, 256>>>(Wq, Wk);
    prep_x_kernel<<<8192, 256>>>(x);

    cudaFuncSetAttribute(Attention_75402445849133_kernel,
                         cudaFuncAttributeMaxDynamicSharedMemorySize, SMEM_TOTAL);
    dim3 grid(8, 128, 1);
    Attention_75402445849133_kernel<<<grid, 256, SMEM_TOTAL>>>(bq, bk, Wo, bo, out);
}